// round 13
// baseline (speedup 1.0000x reference)
#include <cuda_runtime.h>
#include <cuda_fp16.h>
#include <stdint.h>
#include <math.h>

#define N_TOK   8192
#define DM      1024
#define DH      128

// log2(e)/sqrt(128): folded so P = exp(s_true) = 2^(s_computed)
#define QSCALE 0.12751743011447976f

// ---------------------------------------------------------------------------
// Device scratch (allocation-free)
// ---------------------------------------------------------------------------
__device__ __half  gW [3 * DM * DH];          // fp16 weights (Wq pre-scaled by QSCALE)
__device__ __half  gQ [N_TOK * DH];
__device__ __half  gK [N_TOK * DH];
__device__ __half  gV [N_TOK * DH];

// ---------------------------------------------------------------------------
// PTX helpers (baseline PTX only — no sm_103a features)
// ---------------------------------------------------------------------------
__device__ __forceinline__ uint32_t smem_to_u32(const void* p) {
    uint32_t a;
    asm("{ .reg .u64 t; cvta.to.shared.u64 t, %1; cvt.u32.u64 %0, t; }" : "=r"(a) : "l"(p));
    return a;
}
__device__ __forceinline__ void ldsm4(uint32_t& r0, uint32_t& r1, uint32_t& r2, uint32_t& r3,
                                      uint32_t addr) {
    asm volatile("ldmatrix.sync.aligned.m8n8.x4.shared.b16 {%0,%1,%2,%3}, [%4];"
                 : "=r"(r0), "=r"(r1), "=r"(r2), "=r"(r3) : "r"(addr));
}
__device__ __forceinline__ void ldsm4t(uint32_t& r0, uint32_t& r1, uint32_t& r2, uint32_t& r3,
                                       uint32_t addr) {
    asm volatile("ldmatrix.sync.aligned.m8n8.x4.trans.shared.b16 {%0,%1,%2,%3}, [%4];"
                 : "=r"(r0), "=r"(r1), "=r"(r2), "=r"(r3) : "r"(addr));
}
__device__ __forceinline__ void mma_f16(float* d,
                                        uint32_t a0, uint32_t a1, uint32_t a2, uint32_t a3,
                                        uint32_t b0, uint32_t b1) {
    asm volatile("mma.sync.aligned.m16n8k16.row.col.f32.f16.f16.f32 "
                 "{%0,%1,%2,%3}, {%4,%5,%6,%7}, {%8,%9}, {%0,%1,%2,%3};"
                 : "+f"(d[0]), "+f"(d[1]), "+f"(d[2]), "+f"(d[3])
                 : "r"(a0), "r"(a1), "r"(a2), "r"(a3), "r"(b0), "r"(b1));
}
__device__ __forceinline__ uint32_t packh(float lo, float hi) {
    uint32_t r;
    asm("cvt.rn.f16x2.f32 %0, %1, %2;" : "=r"(r) : "f"(hi), "f"(lo));
    return r;
}
__device__ __forceinline__ uint32_t ex2h2(uint32_t x) {
    uint32_t r;
    asm("ex2.approx.f16x2 %0, %1;" : "=r"(r) : "r"(x));
    return r;
}
__device__ __forceinline__ void cpa16(uint32_t saddr, const void* g) {
    asm volatile("cp.async.cg.shared.global [%0], [%1], 16;" :: "r"(saddr), "l"(g));
}
#define CP_COMMIT() asm volatile("cp.async.commit_group;" ::: "memory")
#define CP_WAIT0()  asm volatile("cp.async.wait_group 0;" ::: "memory")

// ---------------------------------------------------------------------------
// wsplit: W fp32 -> fp16; Wq pre-scaled by QSCALE.
// ---------------------------------------------------------------------------
__global__ __launch_bounds__(256) void wsplit_kernel(
    const float* __restrict__ Wq, const float* __restrict__ Wk, const float* __restrict__ Wv)
{
    const int m = blockIdx.y;
    const float* W = (m == 0) ? Wq : (m == 1) ? Wk : Wv;
    const float sc = (m == 0) ? QSCALE : 1.0f;
    int idx = blockIdx.x * 256 + threadIdx.x;
    float4 v = ((const float4*)W)[idx];
    ((uint2*)gW)[m * (DM * DH / 4) + idx] =
        make_uint2(packh(v.x * sc, v.y * sc), packh(v.z * sc, v.w * sc));
}

// ---------------------------------------------------------------------------
// QKV projection on mma.sync, single-term fp16 (X W), fp16 outputs.
// Reads fp32 x directly, converts to fp16 during the smem store.
// ---------------------------------------------------------------------------
#define XSTR 72
#define WSTR 136
#define QKV_SMEM ((128 * XSTR + 64 * WSTR) * 2)

__global__ __launch_bounds__(256, 2) void qkv_mma_kernel(
    const float* __restrict__ x,
    const float* __restrict__ bq, const float* __restrict__ bk, const float* __restrict__ bv)
{
    extern __shared__ __half smh[];
    __half* Xh = smh;
    __half* Wh = Xh + 128 * XSTR;

    const int t  = threadIdx.x;
    const int w  = t >> 5;
    const int l  = t & 31;
    const int m0 = blockIdx.x * 128;
    const int mat = blockIdx.y;

    const __half* Wg = gW + (size_t)mat * DM * DH;
    const float* bias = (mat == 0) ? bq : (mat == 1) ? bk : bv;
    const float bsc = (mat == 0) ? QSCALE : 1.0f;
    __half* D = (mat == 0) ? gQ : (mat == 1) ? gK : gV;

    const uint32_t sb = smem_to_u32(smh);
    const uint32_t lrow = l & 15;
    const uint32_t lcol = (uint32_t)((l >> 4) << 3);
    const uint32_t xh_b = sb + (w * 16 * XSTR + lrow * XSTR + lcol) * 2;
    const uint32_t wh_b = sb + (128 * XSTR) * 2 + (lrow * WSTR + lcol) * 2;

    float acc[16][4];
    #pragma unroll
    for (int i = 0; i < 16; i++)
        #pragma unroll
        for (int j = 0; j < 4; j++) acc[i][j] = 0.f;

    for (int k0 = 0; k0 < DM; k0 += 64) {
        __syncthreads();
        #pragma unroll
        for (int i = 0; i < 4; i++) {
            int idx = t + i * 256;
            int r = idx >> 3;
            int c = (idx & 7) << 3;
            const float4* xp = (const float4*)&x[(size_t)(m0 + r) * DM + k0 + c];
            float4 v0 = xp[0];
            float4 v1 = xp[1];
            uint4 u;
            u.x = packh(v0.x, v0.y);
            u.y = packh(v0.z, v0.w);
            u.z = packh(v1.x, v1.y);
            u.w = packh(v1.z, v1.w);
            *(uint4*)&Xh[r * XSTR + c] = u;
        }
        #pragma unroll
        for (int i = 0; i < 4; i++) {
            int idx = t + i * 256;
            int r = idx >> 4;
            int c = (idx & 15) << 3;
            *(uint4*)&Wh[r * WSTR + c] = *(const uint4*)&Wg[(size_t)(k0 + r) * DH + c];
        }
        __syncthreads();

        #pragma unroll
        for (int kt = 0; kt < 4; kt++) {
            uint32_t a0, a1, a2, a3;
            ldsm4(a0, a1, a2, a3, xh_b + kt * 32);
            #pragma unroll
            for (int nt2 = 0; nt2 < 8; nt2++) {
                uint32_t b0, b1, b2, b3;
                uint32_t rofs = (uint32_t)(kt * 16 * WSTR * 2 + nt2 * 32);
                ldsm4t(b0, b1, b2, b3, wh_b + rofs);
                mma_f16(acc[2 * nt2],     a0, a1, a2, a3, b0, b1);
                mma_f16(acc[2 * nt2 + 1], a0, a1, a2, a3, b2, b3);
            }
        }
    }

    const int row0 = m0 + 16 * w + (l >> 2);
    const int row1 = row0 + 8;
    #pragma unroll
    for (int nt = 0; nt < 16; nt++) {
        int col = 8 * nt + 2 * (l & 3);
        float b0 = bias[col] * bsc;
        float b1 = bias[col + 1] * bsc;
        *(uint32_t*)&D[(size_t)row0 * DH + col] = packh(acc[nt][0] + b0, acc[nt][1] + b1);
        *(uint32_t*)&D[(size_t)row1 * DH + col] = packh(acc[nt][2] + b0, acc[nt][3] + b1);
    }
}

// ---------------------------------------------------------------------------
// Attention: CTA = 64 q-rows x ALL keys (grid 128, 64 chunks of 128 keys).
// Warp = 16 rows (wm 0..3) x 64-key half (kh 0..1). Q frags hoisted once.
// S = Q K^T (log2-scaled); P = 2^S via ex2.f16x2; O += P V; rowsums via
// tensor core (V pad col 128 = 1.0). Softmax completes IN-KERNEL: kh=1 warps
// dump partial O + rowsums to smem, kh=0 warps merge + normalize + store out.
// ---------------------------------------------------------------------------
#define SSTRIDE 136
#define QTB   (64 * SSTRIDE * 2)            // Q tile bytes (64 rows)
#define KVT   (128 * SSTRIDE * 2)           // K or V tile bytes (128 keys)
#define BUFS  (2 * KVT)                     // K + V per buffer
#define SMEM_ATTN (QTB + 2 * BUFS + 512)    // Q + 2 buffers + ldsm-overrun guard

__global__ __launch_bounds__(256, 1) void attn_kernel(float* __restrict__ out)
{
    extern __shared__ __half smh[];

    const int t  = threadIdx.x;
    const int w  = t >> 5;
    const int l  = t & 31;
    const int wm = w & 3;        // M-slice: rows wm*16 .. wm*16+15 (of 64)
    const int kh = w >> 2;       // key-half within chunk
    const int q0 = blockIdx.x * 64;

    const uint32_t sb = smem_to_u32(smh);
    const uint32_t lrow = l & 15;
    const uint32_t lcol = (uint32_t)((l >> 4) << 3);
    const uint32_t lofs = (lrow * SSTRIDE + lcol) * 2;

    const uint32_t q_b  = sb + (uint32_t)(wm * 16 * SSTRIDE) * 2 + lofs;
    const uint32_t buf0 = sb + QTB;
    const uint32_t khofs = (uint32_t)(kh * 64 * SSTRIDE) * 2;

    // V pad columns: col 128 = 1.0 (rowsum), 129-135 = 0. cp.async only
    // writes cols 0-127, so no race; persists across reloads.
    {
        int buf = t & 1;
        int r = t >> 1;
        uint32_t pa = buf0 + (uint32_t)buf * BUFS + KVT + (uint32_t)(r * SSTRIDE + 128) * 2;
        *(uint4*)((char*)smh + (pa - sb)) = make_uint4(0x00003C00u, 0u, 0u, 0u);
    }

    // ---- prologue: async loads (Q 64 rows; chunk 0 K/V) ----
    #pragma unroll
    for (int i = 0; i < 4; i++) {
        int idx = t + i * 256;
        int r = idx >> 4;
        int c = (idx & 15) << 3;
        cpa16(sb + (uint32_t)(r * SSTRIDE + c) * 2, gQ + (size_t)(q0 + r) * DH + c);
    }
    #pragma unroll
    for (int i = 0; i < 8; i++) {
        int idx = t + i * 256;
        int r = idx >> 4;
        int c = (idx & 15) << 3;
        size_t g = (size_t)r * DH + c;
        uint32_t s = buf0 + (uint32_t)(r * SSTRIDE + c) * 2;
        cpa16(s,       gK + g);
        cpa16(s + KVT, gV + g);
    }
    CP_COMMIT();
    CP_WAIT0();
    __syncthreads();

    // ---- hoist Q fragments (constant across chunks) ----
    uint32_t a[8][4];
    #pragma unroll
    for (int kt = 0; kt < 8; kt++)
        ldsm4(a[kt][0], a[kt][1], a[kt][2], a[kt][3], q_b + kt * 32);

    float o[16][4];
    #pragma unroll
    for (int i = 0; i < 16; i++)
        #pragma unroll
        for (int j = 0; j < 4; j++) o[i][j] = 0.f;
    float osum[4] = {0.f, 0.f, 0.f, 0.f};

    for (int ch = 0; ch < 64; ch++) {
        const uint32_t cbuf = buf0 + (uint32_t)(ch & 1) * BUFS;
        const uint32_t k_b = cbuf + khofs + lofs;
        const uint32_t v_b = cbuf + KVT + khofs + lofs;

        if (ch < 63) {
            const uint32_t nbuf = buf0 + (uint32_t)((ch + 1) & 1) * BUFS;
            const int kb = (ch + 1) * 128;
            #pragma unroll
            for (int i = 0; i < 8; i++) {
                int idx = t + i * 256;
                int r = idx >> 4;
                int c = (idx & 15) << 3;
                size_t g = (size_t)(kb + r) * DH + c;
                uint32_t s = nbuf + (uint32_t)(r * SSTRIDE + c) * 2;
                cpa16(s,       gK + g);
                cpa16(s + KVT, gV + g);
            }
            CP_COMMIT();
        }

        // ---- S = Q K^T : 16 rows x 64 keys per warp ----
        float s[8][4];
        #pragma unroll
        for (int i = 0; i < 8; i++)
            #pragma unroll
            for (int j = 0; j < 4; j++) s[i][j] = 0.f;

        #pragma unroll
        for (int kt = 0; kt < 8; kt++) {
            #pragma unroll
            for (int nt2 = 0; nt2 < 4; nt2++) {
                uint32_t b0, b1, b2, b3;
                ldsm4(b0, b1, b2, b3, k_b + (uint32_t)(nt2 * 16 * SSTRIDE * 2 + kt * 32));
                mma_f16(s[2 * nt2],     a[kt][0], a[kt][1], a[kt][2], a[kt][3], b0, b2);
                mma_f16(s[2 * nt2 + 1], a[kt][0], a[kt][1], a[kt][2], a[kt][3], b1, b3);
            }
        }

        // ---- P = 2^S (pack fp32->fp16x2, ex2.f16x2) ----
        uint32_t ph[8][2];
        #pragma unroll
        for (int nt = 0; nt < 8; nt++) {
            ph[nt][0] = ex2h2(packh(s[nt][0], s[nt][1]));
            ph[nt][1] = ex2h2(packh(s[nt][2], s[nt][3]));
        }

        // ---- O += P V (warp's 64 keys: kt 0..3) ----
        #pragma unroll
        for (int kt = 0; kt < 4; kt++) {
            uint32_t p0 = ph[2 * kt][0], p1 = ph[2 * kt][1];
            uint32_t p2 = ph[2 * kt + 1][0], p3 = ph[2 * kt + 1][1];
            #pragma unroll
            for (int nt2 = 0; nt2 < 8; nt2++) {
                uint32_t b0, b1, b2, b3;
                ldsm4t(b0, b1, b2, b3, v_b + (uint32_t)(kt * 16 * SSTRIDE * 2 + nt2 * 32));
                mma_f16(o[2 * nt2],     p0, p1, p2, p3, b0, b1);
                mma_f16(o[2 * nt2 + 1], p0, p1, p2, p3, b2, b3);
            }
            // rowsum column (V pad col 128 = ones); upper frags unused
            uint32_t b0, b1, b2, b3;
            ldsm4t(b0, b1, b2, b3, v_b + (uint32_t)(kt * 16 * SSTRIDE * 2 + 256));
            mma_f16(osum, p0, p1, p2, p3, b0, b1);
        }

        CP_WAIT0();
        __syncthreads();
    }

    // ---- in-kernel combine + normalize (reuse buffer smem) ----
    float* sp    = (float*)((char*)smh + QTB);          // rowsums [2][64]
    float* opart = (float*)((char*)smh + QTB + 1024);   // kh=1 O: [64][128] fp32

    const int row0 = wm * 16 + (l >> 2);
    const int row1 = row0 + 8;
    if ((l & 3) == 0) {
        sp[kh * 64 + row0] = osum[0];
        sp[kh * 64 + row1] = osum[2];
    }
    if (kh == 1) {
        #pragma unroll
        for (int nt = 0; nt < 16; nt++) {
            int col = 8 * nt + 2 * (l & 3);
            *(float2*)&opart[row0 * DH + col] = make_float2(o[nt][0], o[nt][1]);
            *(float2*)&opart[row1 * DH + col] = make_float2(o[nt][2], o[nt][3]);
        }
    }
    __syncthreads();
    if (kh == 0) {
        float inv0 = 1.0f / (sp[row0] + sp[64 + row0]);
        float inv1 = 1.0f / (sp[row1] + sp[64 + row1]);
        #pragma unroll
        for (int nt = 0; nt < 16; nt++) {
            int col = 8 * nt + 2 * (l & 3);
            float2 p0 = *(float2*)&opart[row0 * DH + col];
            float2 p1 = *(float2*)&opart[row1 * DH + col];
            float2 r0 = make_float2((o[nt][0] + p0.x) * inv0, (o[nt][1] + p0.y) * inv0);
            float2 r1 = make_float2((o[nt][2] + p1.x) * inv1, (o[nt][3] + p1.y) * inv1);
            *(float2*)&out[(size_t)(q0 + row0) * DH + col] = r0;
            *(float2*)&out[(size_t)(q0 + row1) * DH + col] = r1;
        }
    }
}

// ---------------------------------------------------------------------------
extern "C" void kernel_launch(void* const* d_in, const int* in_sizes, int n_in,
                              void* d_out, int out_size)
{
    const float* x  = (const float*)d_in[0];
    const float* Wq = (const float*)d_in[1];
    const float* bq = (const float*)d_in[2];
    const float* Wk = (const float*)d_in[3];
    const float* bk = (const float*)d_in[4];
    const float* Wv = (const float*)d_in[5];
    const float* bv = (const float*)d_in[6];
    float* out = (float*)d_out;

    dim3 gw(DM * DH / 4 / 256, 3);
    wsplit_kernel<<<gw, 256>>>(Wq, Wk, Wv);

    cudaFuncSetAttribute(qkv_mma_kernel, cudaFuncAttributeMaxDynamicSharedMemorySize, QKV_SMEM);
    dim3 g1(N_TOK / 128, 3);
    qkv_mma_kernel<<<g1, 256, QKV_SMEM>>>(x, bq, bk, bv);

    cudaFuncSetAttribute(attn_kernel, cudaFuncAttributeMaxDynamicSharedMemorySize, SMEM_ATTN);
    attn_kernel<<<N_TOK / 64, 256, SMEM_ATTN>>>(out);
}

// round 14
// speedup vs baseline: 1.1820x; 1.1820x over previous
#include <cuda_runtime.h>
#include <cuda_fp16.h>
#include <stdint.h>
#include <math.h>

#define N_TOK   8192
#define DM      1024
#define DH      128

// log2(e)/sqrt(128): folded so P = exp(s_true) = 2^(s_computed)
#define QSCALE 0.12751743011447976f

// ---------------------------------------------------------------------------
// Device scratch (allocation-free)
// ---------------------------------------------------------------------------
__device__ __half  gW [3 * DM * DH];          // fp16 weights (Wq pre-scaled by QSCALE)
__device__ __half  gQ [N_TOK * DH];
__device__ __half  gK [N_TOK * DH];
__device__ __half  gV [N_TOK * DH];
__device__ float   gOp[4 * N_TOK * DH];       // 4 key-split partials
__device__ float   gSum[4 * N_TOK];

// ---------------------------------------------------------------------------
// PTX helpers (baseline PTX only — no sm_103a features)
// ---------------------------------------------------------------------------
__device__ __forceinline__ uint32_t smem_to_u32(const void* p) {
    uint32_t a;
    asm("{ .reg .u64 t; cvta.to.shared.u64 t, %1; cvt.u32.u64 %0, t; }" : "=r"(a) : "l"(p));
    return a;
}
__device__ __forceinline__ void ldsm4(uint32_t& r0, uint32_t& r1, uint32_t& r2, uint32_t& r3,
                                      uint32_t addr) {
    asm volatile("ldmatrix.sync.aligned.m8n8.x4.shared.b16 {%0,%1,%2,%3}, [%4];"
                 : "=r"(r0), "=r"(r1), "=r"(r2), "=r"(r3) : "r"(addr));
}
__device__ __forceinline__ void ldsm4t(uint32_t& r0, uint32_t& r1, uint32_t& r2, uint32_t& r3,
                                       uint32_t addr) {
    asm volatile("ldmatrix.sync.aligned.m8n8.x4.trans.shared.b16 {%0,%1,%2,%3}, [%4];"
                 : "=r"(r0), "=r"(r1), "=r"(r2), "=r"(r3) : "r"(addr));
}
__device__ __forceinline__ void mma_f16(float* d,
                                        uint32_t a0, uint32_t a1, uint32_t a2, uint32_t a3,
                                        uint32_t b0, uint32_t b1) {
    asm volatile("mma.sync.aligned.m16n8k16.row.col.f32.f16.f16.f32 "
                 "{%0,%1,%2,%3}, {%4,%5,%6,%7}, {%8,%9}, {%0,%1,%2,%3};"
                 : "+f"(d[0]), "+f"(d[1]), "+f"(d[2]), "+f"(d[3])
                 : "r"(a0), "r"(a1), "r"(a2), "r"(a3), "r"(b0), "r"(b1));
}
__device__ __forceinline__ uint32_t packh(float lo, float hi) {
    uint32_t r;
    asm("cvt.rn.f16x2.f32 %0, %1, %2;" : "=r"(r) : "f"(hi), "f"(lo));
    return r;
}
__device__ __forceinline__ uint32_t ex2h2(uint32_t x) {
    uint32_t r;
    asm("ex2.approx.f16x2 %0, %1;" : "=r"(r) : "r"(x));
    return r;
}
__device__ __forceinline__ void cpa16(uint32_t saddr, const void* g) {
    asm volatile("cp.async.cg.shared.global [%0], [%1], 16;" :: "r"(saddr), "l"(g));
}
#define CP_COMMIT() asm volatile("cp.async.commit_group;" ::: "memory")
#define CP_WAIT0()  asm volatile("cp.async.wait_group 0;" ::: "memory")

// ---------------------------------------------------------------------------
// wsplit: W fp32 -> fp16; Wq pre-scaled by QSCALE.
// ---------------------------------------------------------------------------
__global__ __launch_bounds__(256) void wsplit_kernel(
    const float* __restrict__ Wq, const float* __restrict__ Wk, const float* __restrict__ Wv)
{
    const int m = blockIdx.y;
    const float* W = (m == 0) ? Wq : (m == 1) ? Wk : Wv;
    const float sc = (m == 0) ? QSCALE : 1.0f;
    int idx = blockIdx.x * 256 + threadIdx.x;
    float4 v = ((const float4*)W)[idx];
    ((uint2*)gW)[m * (DM * DH / 4) + idx] =
        make_uint2(packh(v.x * sc, v.y * sc), packh(v.z * sc, v.w * sc));
}

// ---------------------------------------------------------------------------
// QKV projection on mma.sync, single-term fp16 (X W), fp16 outputs.
// Reads fp32 x directly, converts to fp16 during the smem store.
// ---------------------------------------------------------------------------
#define XSTR 72
#define WSTR 136
#define QKV_SMEM ((128 * XSTR + 64 * WSTR) * 2)

__global__ __launch_bounds__(256, 2) void qkv_mma_kernel(
    const float* __restrict__ x,
    const float* __restrict__ bq, const float* __restrict__ bk, const float* __restrict__ bv)
{
    extern __shared__ __half smh[];
    __half* Xh = smh;
    __half* Wh = Xh + 128 * XSTR;

    const int t  = threadIdx.x;
    const int w  = t >> 5;
    const int l  = t & 31;
    const int m0 = blockIdx.x * 128;
    const int mat = blockIdx.y;

    const __half* Wg = gW + (size_t)mat * DM * DH;
    const float* bias = (mat == 0) ? bq : (mat == 1) ? bk : bv;
    const float bsc = (mat == 0) ? QSCALE : 1.0f;
    __half* D = (mat == 0) ? gQ : (mat == 1) ? gK : gV;

    const uint32_t sb = smem_to_u32(smh);
    const uint32_t lrow = l & 15;
    const uint32_t lcol = (uint32_t)((l >> 4) << 3);
    const uint32_t xh_b = sb + (w * 16 * XSTR + lrow * XSTR + lcol) * 2;
    const uint32_t wh_b = sb + (128 * XSTR) * 2 + (lrow * WSTR + lcol) * 2;

    float acc[16][4];
    #pragma unroll
    for (int i = 0; i < 16; i++)
        #pragma unroll
        for (int j = 0; j < 4; j++) acc[i][j] = 0.f;

    for (int k0 = 0; k0 < DM; k0 += 64) {
        __syncthreads();
        #pragma unroll
        for (int i = 0; i < 4; i++) {
            int idx = t + i * 256;
            int r = idx >> 3;
            int c = (idx & 7) << 3;
            const float4* xp = (const float4*)&x[(size_t)(m0 + r) * DM + k0 + c];
            float4 v0 = xp[0];
            float4 v1 = xp[1];
            uint4 u;
            u.x = packh(v0.x, v0.y);
            u.y = packh(v0.z, v0.w);
            u.z = packh(v1.x, v1.y);
            u.w = packh(v1.z, v1.w);
            *(uint4*)&Xh[r * XSTR + c] = u;
        }
        #pragma unroll
        for (int i = 0; i < 4; i++) {
            int idx = t + i * 256;
            int r = idx >> 4;
            int c = (idx & 15) << 3;
            *(uint4*)&Wh[r * WSTR + c] = *(const uint4*)&Wg[(size_t)(k0 + r) * DH + c];
        }
        __syncthreads();

        #pragma unroll
        for (int kt = 0; kt < 4; kt++) {
            uint32_t a0, a1, a2, a3;
            ldsm4(a0, a1, a2, a3, xh_b + kt * 32);
            #pragma unroll
            for (int nt2 = 0; nt2 < 8; nt2++) {
                uint32_t b0, b1, b2, b3;
                uint32_t rofs = (uint32_t)(kt * 16 * WSTR * 2 + nt2 * 32);
                ldsm4t(b0, b1, b2, b3, wh_b + rofs);
                mma_f16(acc[2 * nt2],     a0, a1, a2, a3, b0, b1);
                mma_f16(acc[2 * nt2 + 1], a0, a1, a2, a3, b2, b3);
            }
        }
    }

    const int row0 = m0 + 16 * w + (l >> 2);
    const int row1 = row0 + 8;
    #pragma unroll
    for (int nt = 0; nt < 16; nt++) {
        int col = 8 * nt + 2 * (l & 3);
        float b0 = bias[col] * bsc;
        float b1 = bias[col + 1] * bsc;
        *(uint32_t*)&D[(size_t)row0 * DH + col] = packh(acc[nt][0] + b0, acc[nt][1] + b1);
        *(uint32_t*)&D[(size_t)row1 * DH + col] = packh(acc[nt][2] + b0, acc[nt][3] + b1);
    }
}

// ---------------------------------------------------------------------------
// Attention: CTA = 128 q-rows x quarter of keys (grid 64x4 = 256 CTAs,
// 32 chunks of 64 keys, double-buffered). 2 CTAs/SM (smem ~102.5 KB,
// 128 regs/thread) -> 4 warps/SMSP for latency hiding.
// Warp = 16 rows x full 64-key chunk. S = Q K^T (log2-scaled); P = 2^S via
// ex2.f16x2; O += P V; rowsums via tensor core (V pad col 128 = 1.0).
// Each split writes an independent partial; combine sums 4.
// ---------------------------------------------------------------------------
#define SSTRIDE 136
#define QTB   (128 * SSTRIDE * 2)           // Q tile bytes (128 rows)
#define KVT   (64 * SSTRIDE * 2)            // K or V tile bytes (64 keys)
#define BUFS  (2 * KVT)                     // K + V per buffer
#define SMEM_ATTN (QTB + 2 * BUFS + 512)    // Q + 2 buffers + ldsm-overrun guard

__global__ __launch_bounds__(256, 2) void attn_kernel()
{
    extern __shared__ __half smh[];

    const int t  = threadIdx.x;
    const int w  = t >> 5;
    const int l  = t & 31;
    const int q0 = blockIdx.x * 128;
    const int split  = blockIdx.y;
    const int kstart = split * (N_TOK / 4);

    const uint32_t sb = smem_to_u32(smh);
    const uint32_t lrow = l & 15;
    const uint32_t lcol = (uint32_t)((l >> 4) << 3);
    const uint32_t lofs = (lrow * SSTRIDE + lcol) * 2;

    const uint32_t q_b  = sb + (uint32_t)(w * 16 * SSTRIDE) * 2 + lofs;
    const uint32_t buf0 = sb + QTB;

    // V pad columns: col 128 = 1.0 (rowsum), 129-135 = 0. cp.async only
    // writes cols 0-127, so no race; persists across reloads.
    if (t < 128) {
        int buf = t >> 6;
        int r = t & 63;
        uint32_t pa = buf0 + (uint32_t)buf * BUFS + KVT + (uint32_t)(r * SSTRIDE + 128) * 2;
        *(uint4*)((char*)smh + (pa - sb)) = make_uint4(0x00003C00u, 0u, 0u, 0u);
    }

    // ---- prologue: Q (128 rows) + chunk-0 K/V (64 keys) ----
    #pragma unroll
    for (int i = 0; i < 8; i++) {
        int idx = t + i * 256;
        int r = idx >> 4;
        int c = (idx & 15) << 3;
        cpa16(sb + (uint32_t)(r * SSTRIDE + c) * 2, gQ + (size_t)(q0 + r) * DH + c);
    }
    #pragma unroll
    for (int i = 0; i < 4; i++) {
        int idx = t + i * 256;
        int r = idx >> 4;
        int c = (idx & 15) << 3;
        size_t g = (size_t)(kstart + r) * DH + c;
        uint32_t s = buf0 + (uint32_t)(r * SSTRIDE + c) * 2;
        cpa16(s,       gK + g);
        cpa16(s + KVT, gV + g);
    }
    CP_COMMIT();
    CP_WAIT0();
    __syncthreads();

    float o[16][4];
    #pragma unroll
    for (int i = 0; i < 16; i++)
        #pragma unroll
        for (int j = 0; j < 4; j++) o[i][j] = 0.f;
    float osum[4] = {0.f, 0.f, 0.f, 0.f};

    for (int ch = 0; ch < 32; ch++) {
        const uint32_t cbuf = buf0 + (uint32_t)(ch & 1) * BUFS;
        const uint32_t k_b = cbuf + lofs;
        const uint32_t v_b = cbuf + KVT + lofs;

        if (ch < 31) {
            const uint32_t nbuf = buf0 + (uint32_t)((ch + 1) & 1) * BUFS;
            const int kb = kstart + (ch + 1) * 64;
            #pragma unroll
            for (int i = 0; i < 4; i++) {
                int idx = t + i * 256;
                int r = idx >> 4;
                int c = (idx & 15) << 3;
                size_t g = (size_t)(kb + r) * DH + c;
                uint32_t s = nbuf + (uint32_t)(r * SSTRIDE + c) * 2;
                cpa16(s,       gK + g);
                cpa16(s + KVT, gV + g);
            }
            CP_COMMIT();
        }

        // ---- S = Q K^T : 16 rows x 64 keys per warp ----
        float s[8][4];
        #pragma unroll
        for (int i = 0; i < 8; i++)
            #pragma unroll
            for (int j = 0; j < 4; j++) s[i][j] = 0.f;

        #pragma unroll
        for (int kt = 0; kt < 8; kt++) {
            uint32_t a0, a1, a2, a3;
            ldsm4(a0, a1, a2, a3, q_b + kt * 32);
            #pragma unroll
            for (int nt2 = 0; nt2 < 4; nt2++) {
                uint32_t b0, b1, b2, b3;
                ldsm4(b0, b1, b2, b3, k_b + (uint32_t)(nt2 * 16 * SSTRIDE * 2 + kt * 32));
                mma_f16(s[2 * nt2],     a0, a1, a2, a3, b0, b2);
                mma_f16(s[2 * nt2 + 1], a0, a1, a2, a3, b1, b3);
            }
        }

        // ---- P = 2^S (pack fp32->fp16x2, ex2.f16x2) ----
        uint32_t ph[8][2];
        #pragma unroll
        for (int nt = 0; nt < 8; nt++) {
            ph[nt][0] = ex2h2(packh(s[nt][0], s[nt][1]));
            ph[nt][1] = ex2h2(packh(s[nt][2], s[nt][3]));
        }

        // ---- O += P V (64 keys: kt 0..3) ----
        #pragma unroll
        for (int kt = 0; kt < 4; kt++) {
            uint32_t p0 = ph[2 * kt][0], p1 = ph[2 * kt][1];
            uint32_t p2 = ph[2 * kt + 1][0], p3 = ph[2 * kt + 1][1];
            #pragma unroll
            for (int nt2 = 0; nt2 < 8; nt2++) {
                uint32_t b0, b1, b2, b3;
                ldsm4t(b0, b1, b2, b3, v_b + (uint32_t)(kt * 16 * SSTRIDE * 2 + nt2 * 32));
                mma_f16(o[2 * nt2],     p0, p1, p2, p3, b0, b1);
                mma_f16(o[2 * nt2 + 1], p0, p1, p2, p3, b2, b3);
            }
            // rowsum column (V pad col 128 = ones); upper frags unused
            uint32_t b0, b1, b2, b3;
            ldsm4t(b0, b1, b2, b3, v_b + (uint32_t)(kt * 16 * SSTRIDE * 2 + 256));
            mma_f16(osum, p0, p1, p2, p3, b0, b1);
        }

        CP_WAIT0();
        __syncthreads();
    }

    // ---- epilogue: partial O + rowsums for this split ----
    const int row0 = 16 * w + (l >> 2);
    const int row1 = row0 + 8;
    if ((l & 3) == 0) {
        gSum[split * N_TOK + q0 + row0] = osum[0];
        gSum[split * N_TOK + q0 + row1] = osum[2];
    }
    float* op = gOp + (size_t)split * (N_TOK * DH);
    #pragma unroll
    for (int nt = 0; nt < 16; nt++) {
        int col = 8 * nt + 2 * (l & 3);
        *(float2*)&op[(size_t)(q0 + row0) * DH + col] = make_float2(o[nt][0], o[nt][1]);
        *(float2*)&op[(size_t)(q0 + row1) * DH + col] = make_float2(o[nt][2], o[nt][3]);
    }
}

// ---------------------------------------------------------------------------
// Combine: out = (O0 + O1 + O2 + O3) / (s0 + s1 + s2 + s3)
// ---------------------------------------------------------------------------
__global__ __launch_bounds__(256) void combine_kernel(float* __restrict__ out)
{
    int idx = blockIdx.x * 256 + threadIdx.x;
    int r = idx >> 5;
    float inv = 1.0f / (gSum[r] + gSum[N_TOK + r] + gSum[2 * N_TOK + r] + gSum[3 * N_TOK + r]);
    const int STRIDE4 = N_TOK * DH / 4;
    float4 a = ((const float4*)gOp)[idx];
    float4 b = ((const float4*)gOp)[idx + STRIDE4];
    float4 c = ((const float4*)gOp)[idx + 2 * STRIDE4];
    float4 d = ((const float4*)gOp)[idx + 3 * STRIDE4];
    float4 o;
    o.x = (a.x + b.x + c.x + d.x) * inv;
    o.y = (a.y + b.y + c.y + d.y) * inv;
    o.z = (a.z + b.z + c.z + d.z) * inv;
    o.w = (a.w + b.w + c.w + d.w) * inv;
    ((float4*)out)[idx] = o;
}

// ---------------------------------------------------------------------------
extern "C" void kernel_launch(void* const* d_in, const int* in_sizes, int n_in,
                              void* d_out, int out_size)
{
    const float* x  = (const float*)d_in[0];
    const float* Wq = (const float*)d_in[1];
    const float* bq = (const float*)d_in[2];
    const float* Wk = (const float*)d_in[3];
    const float* bk = (const float*)d_in[4];
    const float* Wv = (const float*)d_in[5];
    const float* bv = (const float*)d_in[6];
    float* out = (float*)d_out;

    dim3 gw(DM * DH / 4 / 256, 3);
    wsplit_kernel<<<gw, 256>>>(Wq, Wk, Wv);

    cudaFuncSetAttribute(qkv_mma_kernel, cudaFuncAttributeMaxDynamicSharedMemorySize, QKV_SMEM);
    dim3 g1(N_TOK / 128, 3);
    qkv_mma_kernel<<<g1, 256, QKV_SMEM>>>(x, bq, bk, bv);

    cudaFuncSetAttribute(attn_kernel, cudaFuncAttributeMaxDynamicSharedMemorySize, SMEM_ATTN);
    dim3 g2(N_TOK / 128, 4);
    attn_kernel<<<g2, 256, SMEM_ATTN>>>();

    combine_kernel<<<N_TOK * DH / 4 / 256, 256>>>(out);
}